// round 6
// baseline (speedup 1.0000x reference)
#include <cuda_runtime.h>

// FocalLoss: mean over N of  w * (1-pt)^2 * (-log10(pt)),
//   pt = y==1 ? p : 1-p ;  w = y==1 ? 0.9 : 0.1
// Two-pass deterministic reduction. HBM-bound: ~226 MB read once.
// -log10(pt) = -log2(pt) * log10(2)  -> single MUFU LG2 + FMULs.

#define NBLOCKS 2368
#define NTHREADS 256

__device__ float g_partials[NBLOCKS];

__device__ __forceinline__ float focal_elem(float p, int y) {
    bool pos = (y == 1);
    float pt  = pos ? p : 1.0f - p;
    float om  = 1.0f - pt;
    float w   = pos ? 0.9f : 0.1f;
    // coefficient chain independent of the MUFU result:
    float c   = om * om * w * (-0.30102999566398120f);
    float lg  = __log2f(pt);                 // MUFU LG2 (16 cyc)
    return c * lg;                           // single dependent FMUL after MUFU
}

__global__ __launch_bounds__(NTHREADS)
void focal_partial_kernel(const float* __restrict__ p,
                          const int*   __restrict__ y,
                          int n) {
    const int n4 = n >> 2;
    const float4* __restrict__ p4 = (const float4*)p;
    const int4*   __restrict__ y4 = (const int4*)y;

    float acc0 = 0.0f, acc1 = 0.0f;
    int idx    = blockIdx.x * NTHREADS + threadIdx.x;
    int stride = gridDim.x * NTHREADS;

    int i = idx;
    // main loop: 2 float4 + 2 int4 per trip (4 consecutive 128-bit LDGs -> high MLP)
    for (; i + stride < n4; i += 2 * stride) {
        float4 pa = __ldcs(&p4[i]);
        float4 pb = __ldcs(&p4[i + stride]);
        int4   ya = __ldcs(&y4[i]);
        int4   yb = __ldcs(&y4[i + stride]);
        acc0 += focal_elem(pa.x, ya.x);
        acc0 += focal_elem(pa.y, ya.y);
        acc0 += focal_elem(pa.z, ya.z);
        acc0 += focal_elem(pa.w, ya.w);
        acc1 += focal_elem(pb.x, yb.x);
        acc1 += focal_elem(pb.y, yb.y);
        acc1 += focal_elem(pb.z, yb.z);
        acc1 += focal_elem(pb.w, yb.w);
    }
    // vector remainder (at most one trip)
    for (; i < n4; i += stride) {
        float4 pa = __ldcs(&p4[i]);
        int4   ya = __ldcs(&y4[i]);
        acc0 += focal_elem(pa.x, ya.x);
        acc0 += focal_elem(pa.y, ya.y);
        acc0 += focal_elem(pa.z, ya.z);
        acc0 += focal_elem(pa.w, ya.w);
    }
    // scalar tail (n % 4 elements), handled by block 0 only
    if (blockIdx.x == 0) {
        int t = (n4 << 2) + threadIdx.x;
        if (t < n) acc0 += focal_elem(p[t], y[t]);
    }

    float acc = acc0 + acc1;

    // warp reduce
    #pragma unroll
    for (int off = 16; off > 0; off >>= 1)
        acc += __shfl_down_sync(0xffffffffu, acc, off);

    __shared__ float warp_sums[NTHREADS / 32];
    int lane = threadIdx.x & 31;
    int wid  = threadIdx.x >> 5;
    if (lane == 0) warp_sums[wid] = acc;
    __syncthreads();

    if (wid == 0) {
        float v = (lane < NTHREADS / 32) ? warp_sums[lane] : 0.0f;
        #pragma unroll
        for (int off = 16; off > 0; off >>= 1)
            v += __shfl_down_sync(0xffffffffu, v, off);
        if (lane == 0) g_partials[blockIdx.x] = v;
    }
}

__global__ __launch_bounds__(1024)
void focal_final_kernel(float* __restrict__ out, float inv_n) {
    double acc = 0.0;
    for (int i = threadIdx.x; i < NBLOCKS; i += 1024)
        acc += (double)g_partials[i];

    // warp reduce in double
    #pragma unroll
    for (int off = 16; off > 0; off >>= 1)
        acc += __shfl_down_sync(0xffffffffu, acc, off);

    __shared__ double warp_sums[32];
    int lane = threadIdx.x & 31;
    int wid  = threadIdx.x >> 5;
    if (lane == 0) warp_sums[wid] = acc;
    __syncthreads();

    if (wid == 0) {
        double v = (lane < 32) ? warp_sums[lane] : 0.0;
        #pragma unroll
        for (int off = 16; off > 0; off >>= 1)
            v += __shfl_down_sync(0xffffffffu, v, off);
        if (lane == 0) out[0] = (float)(v * (double)inv_n);
    }
}

extern "C" void kernel_launch(void* const* d_in, const int* in_sizes, int n_in,
                              void* d_out, int out_size) {
    const float* p = (const float*)d_in[0];
    const int*   y = (const int*)d_in[1];
    float* out = (float*)d_out;

    int n = in_sizes[0];      // 28,311,552 for the reference shape

    focal_partial_kernel<<<NBLOCKS, NTHREADS>>>(p, y, n);
    focal_final_kernel<<<1, 1024>>>(out, 1.0f / (float)n);
}

// round 9
// speedup vs baseline: 1.0632x; 1.0632x over previous
#include <cuda_runtime.h>

// FocalLoss: mean over N of  w * (1-pt)^2 * (-log10(pt)),
//   pt = y==1 ? p : 1-p ;  w = y==1 ? 0.9 : 0.1
// Single fused kernel: grid-stride partials + deterministic fixed-point
// atomic reduction (int64, scale 2^32; integer adds commute -> bit-exact
// regardless of block completion order). Last block writes the mean and
// resets the accumulators so the launch is graph-replay-safe.

#define NBLOCKS 2368
#define NTHREADS 256

__device__ unsigned long long g_acc;    // zero-initialized at module load
__device__ unsigned int       g_done;   // zero-initialized at module load

#define FP_SCALE     4294967296.0   // 2^32
#define FP_INV_SCALE (1.0 / 4294967296.0)

__device__ __forceinline__ float focal_elem(float p, int y) {
    bool pos = (y == 1);
    float pt  = pos ? p : 1.0f - p;
    float om  = 1.0f - pt;
    float w   = pos ? 0.9f : 0.1f;
    // coefficient chain independent of the MUFU result:
    float c   = om * om * w * (-0.30102999566398120f);
    float lg  = __log2f(pt);                 // MUFU LG2 (16 cyc)
    return c * lg;                           // single dependent FMUL after MUFU
}

__global__ __launch_bounds__(NTHREADS)
void focal_fused_kernel(const float* __restrict__ p,
                        const int*   __restrict__ y,
                        float* __restrict__ out,
                        int n, float inv_n) {
    const int n4 = n >> 2;
    const float4* __restrict__ p4 = (const float4*)p;
    const int4*   __restrict__ y4 = (const int4*)y;

    float acc0 = 0.0f, acc1 = 0.0f;
    int idx    = blockIdx.x * NTHREADS + threadIdx.x;
    int stride = gridDim.x * NTHREADS;

    int i = idx;
    // main loop: 2 float4 + 2 int4 per trip (4 consecutive 128-bit LDGs -> high MLP)
    for (; i + stride < n4; i += 2 * stride) {
        float4 pa = __ldcs(&p4[i]);
        float4 pb = __ldcs(&p4[i + stride]);
        int4   ya = __ldcs(&y4[i]);
        int4   yb = __ldcs(&y4[i + stride]);
        acc0 += focal_elem(pa.x, ya.x);
        acc0 += focal_elem(pa.y, ya.y);
        acc0 += focal_elem(pa.z, ya.z);
        acc0 += focal_elem(pa.w, ya.w);
        acc1 += focal_elem(pb.x, yb.x);
        acc1 += focal_elem(pb.y, yb.y);
        acc1 += focal_elem(pb.z, yb.z);
        acc1 += focal_elem(pb.w, yb.w);
    }
    // vector remainder (at most one trip)
    for (; i < n4; i += stride) {
        float4 pa = __ldcs(&p4[i]);
        int4   ya = __ldcs(&y4[i]);
        acc0 += focal_elem(pa.x, ya.x);
        acc0 += focal_elem(pa.y, ya.y);
        acc0 += focal_elem(pa.z, ya.z);
        acc0 += focal_elem(pa.w, ya.w);
    }
    // scalar tail (n % 4 elements), handled by block 0 only
    if (blockIdx.x == 0) {
        int t = (n4 << 2) + threadIdx.x;
        if (t < n) acc0 += focal_elem(p[t], y[t]);
    }

    float acc = acc0 + acc1;

    // intra-block reduce (warp shuffle + smem)
    #pragma unroll
    for (int off = 16; off > 0; off >>= 1)
        acc += __shfl_down_sync(0xffffffffu, acc, off);

    __shared__ float warp_sums[NTHREADS / 32];
    int lane = threadIdx.x & 31;
    int wid  = threadIdx.x >> 5;
    if (lane == 0) warp_sums[wid] = acc;
    __syncthreads();

    if (wid == 0) {
        float v = (lane < NTHREADS / 32) ? warp_sums[lane] : 0.0f;
        #pragma unroll
        for (int off = 16; off > 0; off >>= 1)
            v += __shfl_down_sync(0xffffffffu, v, off);

        if (lane == 0) {
            // deterministic fixed-point accumulate (terms are all >= 0)
            unsigned long long q =
                (unsigned long long)__double2ll_rn((double)v * FP_SCALE);
            atomicAdd(&g_acc, q);
            __threadfence();
            unsigned int old = atomicAdd(&g_done, 1u);
            if (old == gridDim.x - 1) {
                // last block: read+reset accumulator, write result, reset counter
                unsigned long long total = atomicExch(&g_acc, 0ULL);
                out[0] = (float)((double)total * FP_INV_SCALE * (double)inv_n);
                g_done = 0u;   // visible to next launch at kernel completion
            }
        }
    }
}

extern "C" void kernel_launch(void* const* d_in, const int* in_sizes, int n_in,
                              void* d_out, int out_size) {
    const float* p = (const float*)d_in[0];
    const int*   y = (const int*)d_in[1];
    float* out = (float*)d_out;

    int n = in_sizes[0];      // 28,311,552 for the reference shape

    focal_fused_kernel<<<NBLOCKS, NTHREADS>>>(p, y, out, n, 1.0f / (float)n);
}